// round 6
// baseline (speedup 1.0000x reference)
#include <cuda_runtime.h>
#include <math.h>
#include <math_constants.h>

#define THREADS 256
#define NBUCKET 32   // atomic spreading: per-address op count = B/NBUCKET

// Bucketed accumulators: bucket row = 256B. soft at [b][0..15],
// hard at [b][32..47] — different L2 sectors, spread across slices.
__device__ float g_acc[NBUCKET][64];

__global__ void init_acc_kernel() {
    g_acc[blockIdx.x][threadIdx.x] = 0.f;   // <<<NBUCKET, 64>>>
}

__global__ void finalize_kernel(float* __restrict__ out_tail, float invB, int E) {
    int t = threadIdx.x;
    if (t < 2 * E) {
        int idx = (t < E) ? t : (32 + (t - E));   // soft | hard slot within bucket row
        float s = 0.f;
        #pragma unroll
        for (int b = 0; b < NBUCKET; b++) s += g_acc[b][idx];
        out_tail[t] = s * invB;
    }
}

// Fast path: E == 16. One block per batch row b.
__global__ __launch_bounds__(THREADS) void fused16_kernel(
    const float* __restrict__ f, const float* __restrict__ x,
    const float* __restrict__ perm, const float* __restrict__ gate,
    const float* __restrict__ bias, float* __restrict__ y,
    int D, int DIN, int P)
{
    constexpr int E = 16;
    extern __shared__ float smem[];
    float* xs     = smem;              // DIN
    float* pw     = xs + DIN;          // 256
    float* logits = pw + 256;          // 16
    float* gp     = logits + 16;       // 16 (16B-aligned when DIN%4==0)

    const int tid = threadIdx.x;
    const int b   = blockIdx.x;

    // Stage x row + mean permutation matrix
    for (int k = tid; k < DIN; k += THREADS) xs[k] = x[(size_t)b * DIN + k];
    const float invP = 1.f / (float)P;
    for (int i = tid; i < 256; i += THREADS) {
        float s = 0.f;
        for (int p = 0; p < P; p++) s += perm[p * 256 + i];
        pw[i] = s * invP;
    }
    __syncthreads();

    // Gate logits: 16 threads per expert, shfl reduce within width-16 groups
    {
        const int e = tid >> 4, lg = tid & 15;
        const float* gr = gate + (size_t)e * DIN;
        float part = 0.f;
        for (int k = lg; k < DIN; k += 16) part += xs[k] * gr[k];
        #pragma unroll
        for (int off = 8; off > 0; off >>= 1)
            part += __shfl_down_sync(0xffffffffu, part, off, 16);
        if (lg == 0) logits[e] = part + bias[e];
    }
    __syncthreads();

    // Top-2 -> masked softmax -> permuted+normalized gates (thread 0)
    if (tid == 0) {
        float v1 = -CUDART_INF_F; int i1 = 0;
        #pragma unroll
        for (int i = 0; i < E; i++) if (logits[i] > v1) { v1 = logits[i]; i1 = i; }
        float v2 = -CUDART_INF_F; int i2 = 0;
        #pragma unroll
        for (int i = 0; i < E; i++) if (i != i1 && logits[i] > v2) { v2 = logits[i]; i2 = i; }
        // faithful tf.where(scattered == 0 -> -inf)
        float m1 = (v1 == 0.f) ? -CUDART_INF_F : v1;
        float m2 = (v2 == 0.f) ? -CUDART_INF_F : v2;
        float m  = fmaxf(m1, m2);
        float e1 = __expf(m1 - m), e2 = __expf(m2 - m);
        float zi = 1.f / (e1 + e2);
        float g1 = e1 * zi, g2 = e2 * zi;
        float raw[E]; float s = 0.f;
        #pragma unroll
        for (int j = 0; j < E; j++) {
            raw[j] = g1 * pw[i1 * E + j] + g2 * pw[i2 * E + j];
            s += raw[j];
        }
        const float rinv = 1.f / s;
        #pragma unroll
        for (int j = 0; j < E; j++) gp[j] = raw[j] * rinv;
    }
    __syncthreads();

    // Lanes 0-31 of warp 0: parallel fire-and-forget atomics into spread buckets.
    if (tid < 32) {
        const int bucket = b & (NBUCKET - 1);
        const int j = tid & 15;
        const float v = gp[j];
        if (tid < 16) atomicAdd(&g_acc[bucket][j], v);
        else          atomicAdd(&g_acc[bucket][32 + j], (v < 1e-5f) ? 0.f : 1.f);
    }

    // Streaming pass over f: 64B per (b,d) via 4x float4, weights in registers
    const float4 w0 = ((const float4*)gp)[0];
    const float4 w1 = ((const float4*)gp)[1];
    const float4 w2 = ((const float4*)gp)[2];
    const float4 w3 = ((const float4*)gp)[3];
    const size_t base = (size_t)b * D * E;
    float* yr = y + (size_t)b * D;
    for (int d = tid; d < D; d += THREADS) {
        const float4* fr = (const float4*)(f + base + (size_t)d * E);
        float4 a0 = fr[0], a1 = fr[1], a2 = fr[2], a3 = fr[3];
        float acc = a0.x * w0.x + a0.y * w0.y + a0.z * w0.z + a0.w * w0.w
                  + a1.x * w1.x + a1.y * w1.y + a1.z * w1.z + a1.w * w1.w
                  + a2.x * w2.x + a2.y * w2.y + a2.z * w2.z + a2.w * w2.w
                  + a3.x * w3.x + a3.y * w3.y + a3.z * w3.z + a3.w * w3.w;
        yr[d] = acc;
    }
}

// Generic fallback (any E <= 32)
__global__ void fused_generic_kernel(
    const float* __restrict__ f, const float* __restrict__ x,
    const float* __restrict__ perm, const float* __restrict__ gate,
    const float* __restrict__ bias, float* __restrict__ y,
    int D, int DIN, int P, int E)
{
    extern __shared__ float smem[];
    float* xs     = smem;
    float* pw     = xs + DIN;
    float* logits = pw + E * E;
    float* gp     = logits + E;
    const int tid = threadIdx.x;
    const int b   = blockIdx.x;

    for (int k = tid; k < DIN; k += blockDim.x) xs[k] = x[(size_t)b * DIN + k];
    const float invP = 1.f / (float)P;
    for (int i = tid; i < E * E; i += blockDim.x) {
        float s = 0.f;
        for (int p = 0; p < P; p++) s += perm[p * E * E + i];
        pw[i] = s * invP;
    }
    __syncthreads();
    for (int e = tid; e < E; e += blockDim.x) {
        float s = 0.f;
        const float* gr = gate + (size_t)e * DIN;
        for (int k = 0; k < DIN; k++) s += xs[k] * gr[k];
        logits[e] = s + bias[e];
    }
    __syncthreads();
    if (tid == 0) {
        float v1 = -CUDART_INF_F; int i1 = 0;
        for (int i = 0; i < E; i++) if (logits[i] > v1) { v1 = logits[i]; i1 = i; }
        float v2 = -CUDART_INF_F; int i2 = 0;
        for (int i = 0; i < E; i++) if (i != i1 && logits[i] > v2) { v2 = logits[i]; i2 = i; }
        float m1 = (v1 == 0.f) ? -CUDART_INF_F : v1;
        float m2 = (v2 == 0.f) ? -CUDART_INF_F : v2;
        float m  = fmaxf(m1, m2);
        float e1 = __expf(m1 - m), e2 = __expf(m2 - m);
        float zi = 1.f / (e1 + e2);
        float g1 = e1 * zi, g2 = e2 * zi;
        float s = 0.f;
        for (int j = 0; j < E; j++) {
            float r = g1 * pw[i1 * E + j] + g2 * pw[i2 * E + j];
            gp[j] = r; s += r;
        }
        const float rinv = 1.f / s;
        const int bucket = b & (NBUCKET - 1);
        for (int j = 0; j < E; j++) {
            float v = gp[j] * rinv;
            gp[j] = v;
            if (j < 32) {
                atomicAdd(&g_acc[bucket][j], v);
                atomicAdd(&g_acc[bucket][32 + j], (v < 1e-5f) ? 0.f : 1.f);
            }
        }
    }
    __syncthreads();
    const size_t base = (size_t)b * D * E;
    for (int d = tid; d < D; d += blockDim.x) {
        const float* fr = f + base + (size_t)d * E;
        float acc = 0.f;
        for (int e = 0; e < E; e++) acc += fr[e] * gp[e];
        y[(size_t)b * D + d] = acc;
    }
}

extern "C" void kernel_launch(void* const* d_in, const int* in_sizes, int n_in,
                              void* d_out, int out_size) {
    const float* f    = (const float*)d_in[0];
    const float* x    = (const float*)d_in[1];
    const float* perm = (const float*)d_in[2];
    const float* gate = (const float*)d_in[3];
    const float* bias = (const float*)d_in[4];

    const int E   = in_sizes[4];
    const int DIN = in_sizes[3] / E;
    const int B   = in_sizes[1] / DIN;
    const int D   = (int)((long long)in_sizes[0] / ((long long)B * E));
    const int P   = in_sizes[2] / (E * E);
    float* y = (float*)d_out;

    init_acc_kernel<<<NBUCKET, 64>>>();   // FIX: was <<<1, 2048>>> (invalid config)

    const size_t smem = (size_t)(DIN + E * E + 2 * E + 8) * sizeof(float);
    if (E == 16 && DIN % 16 == 0 && DIN >= 16)
        fused16_kernel<<<B, THREADS, smem>>>(f, x, perm, gate, bias, y, D, DIN, P);
    else
        fused_generic_kernel<<<B, THREADS, smem>>>(f, x, perm, gate, bias, y, D, DIN, P, E);

    const long long tail = (long long)B * D;
    if ((long long)out_size >= tail + 2LL * E)
        finalize_kernel<<<1, ((2 * E + 31) / 32) * 32>>>(y + tail, 1.f / (float)B, E);
}